// round 11
// baseline (speedup 1.0000x reference)
#include <cuda_runtime.h>
#include <cstdint>

#define Bsz 256
#define Tlen 512
#define Iin 5
#define HH 100
#define G4 400
#define NL 5
#define Oout 3
#define BT (Bsz*Tlen)

typedef unsigned long long ull;

#define FMA2(d, a, b, c) asm("fma.rn.f32x2 %0, %1, %2, %3;" : "=l"(d) : "l"(a), "l"(b), "l"(c))
#define ADDF2(d, a, b)   asm("add.rn.f32x2 %0, %1, %2;" : "=l"(d) : "l"(a), "l"(b))
#define PACK2(d, lo, hi) asm("mov.b64 %0, {%1, %2};" : "=l"(d) : "f"(lo), "f"(hi))
#define UNPACK2(lo, hi, v) asm("mov.b64 {%0, %1}, %2;" : "=f"(lo), "=f"(hi) : "l"(v))

// ---------------------------------------------------------------------------
// Scratch
// ---------------------------------------------------------------------------
__device__ float g_gates[(size_t)BT * G4];
__device__ float g_hA[(size_t)BT * HH];
__device__ float g_hB[(size_t)BT * HH];

__device__ __forceinline__ float sigf(float x) {
    return __fdividef(1.0f, 1.0f + __expf(-x));
}
__device__ __forceinline__ float tanh_(float x) {
    return __fdividef(2.0f, 1.0f + __expf(-2.0f * x)) - 1.0f;
}

// ---------------------------------------------------------------------------
// Kernel 1a: layer-0 input projection (K=5) — round-6 exact
// ---------------------------------------------------------------------------
__global__ void gemm_in0(const float* __restrict__ x,
                         const float* __restrict__ Wih,
                         const float* __restrict__ bias)
{
    int idx = blockIdx.x * blockDim.x + threadIdx.x;
    int m = idx / G4;
    int n = idx - m * G4;
    const float* xr = x + (size_t)m * Iin;
    const float* wr = Wih + (size_t)n * Iin;
    float a = bias[n];
#pragma unroll
    for (int k = 0; k < Iin; k++) a += xr[k] * wr[k];
    g_gates[(size_t)idx] = a;
}

// ---------------------------------------------------------------------------
// Kernel 1b: layers 1..4 input projection — round-6 exact (verified 344us)
// ---------------------------------------------------------------------------
#define GM 64
#define GNJ 7
#define GN (16*GNJ)
#define KP 102
#define GEMM_SMEM ((GM + GN) * KP * 4)

__global__ __launch_bounds__(256)
void gemm_in(int inSel,
             const float* __restrict__ W,
             const float* __restrict__ bias)
{
    extern __shared__ float sm[];
    float* Xs = sm;
    float* Ws = sm + GM * KP;

    const float* X = inSel ? g_hB : g_hA;
    int tid = threadIdx.x;
    int tx = tid & 15;
    int ty = (tid >> 4) & 15;
    size_t m0 = (size_t)blockIdx.x * GM;
    int n0 = blockIdx.y * GN;

    {
        const float2* Xg = (const float2*)(X + m0 * 100);
        for (int idx = tid; idx < GM * 50; idx += 256) {
            int r = idx / 50, c = idx - r * 50;
            float2 v = Xg[(size_t)r * 50 + c];
            *(float2*)&Xs[r * KP + 2 * c] = v;
        }
        const float2* Wg = (const float2*)W;
        for (int idx = tid; idx < GN * 50; idx += 256) {
            int r = idx / 50, c = idx - r * 50;
            int gn = n0 + r;
            float2 v = (gn < G4) ? Wg[(size_t)gn * 50 + c] : make_float2(0.f, 0.f);
            *(float2*)&Ws[r * KP + 2 * c] = v;
        }
    }
    __syncthreads();

    ull acc[4][GNJ];
#pragma unroll
    for (int i = 0; i < 4; i++)
#pragma unroll
        for (int j = 0; j < GNJ; j++) PACK2(acc[i][j], 0.f, 0.f);

    const ull* xrow[4];
#pragma unroll
    for (int i = 0; i < 4; i++) xrow[i] = (const ull*)&Xs[(ty + 16 * i) * KP];
    const ull* wrow[GNJ];
#pragma unroll
    for (int j = 0; j < GNJ; j++) wrow[j] = (const ull*)&Ws[(tx + 16 * j) * KP];

#pragma unroll 5
    for (int k = 0; k < 50; k++) {
        ull dx[4], dw[GNJ];
#pragma unroll
        for (int i = 0; i < 4; i++) dx[i] = xrow[i][k];
#pragma unroll
        for (int j = 0; j < GNJ; j++) dw[j] = wrow[j][k];
#pragma unroll
        for (int i = 0; i < 4; i++)
#pragma unroll
            for (int j = 0; j < GNJ; j++)
                FMA2(acc[i][j], dx[i], dw[j], acc[i][j]);
    }

#pragma unroll
    for (int i = 0; i < 4; i++) {
        size_t m = m0 + ty + 16 * i;
#pragma unroll
        for (int j = 0; j < GNJ; j++) {
            int n = n0 + tx + 16 * j;
            if (n < G4) {
                float lo, hi;
                UNPACK2(lo, hi, acc[i][j]);
                g_gates[m * G4 + n] = lo + hi + bias[n];
            }
        }
    }
}

// ---------------------------------------------------------------------------
// Kernel 2: LSTM recurrence — split-K quad-gate, ONE batch row per block.
// Grid 256 x 800 threads -> 2 independent blocks per SM (50 warps): one
// block's activation/barrier tail overlaps the other's dot. Inner structure
// identical to the verified round-8 kernel, minus the second row.
// Thread u*8 + s*2 + half owns half of gate row s*100+u (13 16B chunks,
// chunk 25 = zero dummy).
// ---------------------------------------------------------------------------
__global__ __launch_bounds__(800, 1)
void lstm_rec(const float* __restrict__ W_hh,   // [400,100]
              int outSel, int storeAll)
{
    __shared__ __align__(16) float hbuf[2][104];   // [parity][unit(+pad)]

    const int tid  = threadIdx.x;
    const int u    = tid >> 3;
    const int s    = (tid >> 1) & 3;    // 0=i 1=f 2=g 3=o
    const int half = tid & 1;
    const int grow = s * 100 + u;
    const int row  = blockIdx.x;        // batch row 0..255
    const int lane = tid & 31;
    const int lb   = lane & ~7;
    const int cbase = 13 * half;

    // half of the weight row -> 26 packed regs (chunk 25 = zeros)
    ull w2[26];
    {
        const float4* wr = (const float4*)(W_hh + (size_t)grow * HH);
#pragma unroll
        for (int i = 0; i < 13; i++) {
            int cc = cbase + i;
            float4 v = (cc < 25) ? wr[cc] : make_float4(0.f, 0.f, 0.f, 0.f);
            PACK2(w2[2 * i],     v.x, v.y);
            PACK2(w2[2 * i + 1], v.z, v.w);
        }
    }

    if (tid < 208) ((float*)hbuf)[tid] = 0.f;   // both parities + padding
    float c = 0.f;                              // live in lanes (tid&7)==0

    const float* gp = g_gates + (size_t)row * Tlen * G4;
    float* hout = outSel ? g_hB : g_hA;
    float* hsrow = hout + (size_t)row * Tlen * HH;

    float pg = gp[grow];                        // all lanes (verified pattern)
    __syncthreads();

    for (int t = 0; t < Tlen; t++) {
        const int p = t & 1;
        const float cur = (half == 0) ? pg : 0.f;   // preact added once/pair

        // half-dot
        ull a0, a1;
        PACK2(a0, cur, 0.f); PACK2(a1, 0.f, 0.f);
        {
            const ulonglong2* hA = (const ulonglong2*)hbuf[p];
#pragma unroll
            for (int i = 0; i < 13; i++) {
                ulonglong2 vA = hA[cbase + i];
                FMA2(a0, w2[2 * i],     vA.x, a0);
                FMA2(a1, w2[2 * i + 1], vA.y, a1);
            }
        }
        // prefetch next step's pre-activation (verified position: after dot,
        // all lanes, unpredicated)
        {
            int tn = (t + 1 < Tlen) ? (t + 1) : t;
            pg = gp[(size_t)tn * G4 + grow];
        }
        ADDF2(a0, a0, a1);
        float q0, q1;
        UNPACK2(q0, q1, a0);
        float part = q0 + q1;

        // combine K halves
        float full = part + __shfl_xor_sync(0xFFFFFFFFu, part, 1);

        // own-gate activation
        float v = (s == 2) ? tanh_(full) : sigf(full);

        // gather f,g,o into octet base lane (both half-lanes hold same value)
        float fv = __shfl_sync(0xFFFFFFFFu, v, lb + 2);
        float gv = __shfl_sync(0xFFFFFFFFu, v, lb + 4);
        float ov = __shfl_sync(0xFFFFFFFFu, v, lb + 6);

        // state update in octet base lane
        const int pn = p ^ 1;
        if ((tid & 7) == 0) {            // s==0, half==0; v = input gate
            c = fv * c + v * gv;
            float h = ov * tanh_(c);
            hbuf[pn][u] = h;
            if (storeAll || t == Tlen - 1) hsrow[(size_t)t * HH + u] = h;
        }
        __syncthreads();
    }
}

// ---------------------------------------------------------------------------
// Kernel 3: BN + MLP head
// ---------------------------------------------------------------------------
__global__ void head_kernel(int inSel,
                            const float* __restrict__ gamma,
                            const float* __restrict__ beta,
                            const float* __restrict__ rmean,
                            const float* __restrict__ rvar,
                            const float* __restrict__ W1, const float* __restrict__ b1,
                            const float* __restrict__ W2, const float* __restrict__ b2,
                            const float* __restrict__ W3, const float* __restrict__ b3,
                            float* __restrict__ out)
{
    __shared__ float xa[HH], ya[HH];
    const float* hseq = inSel ? g_hB : g_hA;
    int b = blockIdx.x, tid = threadIdx.x;

    if (tid < HH) {
        float v = hseq[((size_t)b * Tlen + (Tlen - 1)) * HH + tid];
        xa[tid] = (v - rmean[tid]) * rsqrtf(rvar[tid] + 1e-5f) * gamma[tid] + beta[tid];
    }
    __syncthreads();
    if (tid < HH) {
        float a = b1[tid];
#pragma unroll 4
        for (int k = 0; k < HH; k++) a += xa[k] * W1[(size_t)tid * HH + k];
        ya[tid] = fmaxf(a, 0.0f);
    }
    __syncthreads();
    if (tid < HH) {
        float a = b2[tid];
#pragma unroll 4
        for (int k = 0; k < HH; k++) a += ya[k] * W2[(size_t)tid * HH + k];
        xa[tid] = fmaxf(a, 0.0f);
    }
    __syncthreads();
    if (tid < Oout) {
        float a = b3[tid];
#pragma unroll 4
        for (int k = 0; k < HH; k++) a += xa[k] * W3[(size_t)tid * HH + k];
        out[(size_t)b * Oout + tid] = a;
    }
}

// ---------------------------------------------------------------------------
// kernel_launch
// ---------------------------------------------------------------------------
extern "C" void kernel_launch(void* const* d_in, const int* in_sizes, int n_in,
                              void* d_out, int out_size)
{
    const float* x     = (const float*)d_in[0];
    const float* W_ih0 = (const float*)d_in[1];
    const float* W_hh0 = (const float*)d_in[2];
    const float* b0    = (const float*)d_in[3];
    const float* W_ih  = (const float*)d_in[4];
    const float* W_hh  = (const float*)d_in[5];
    const float* bb    = (const float*)d_in[6];
    const float* gamma = (const float*)d_in[7];
    const float* beta  = (const float*)d_in[8];
    const float* rmean = (const float*)d_in[9];
    const float* rvar  = (const float*)d_in[10];
    const float* W1    = (const float*)d_in[11];
    const float* b1    = (const float*)d_in[12];
    const float* W2    = (const float*)d_in[13];
    const float* b2    = (const float*)d_in[14];
    const float* W3    = (const float*)d_in[15];
    const float* b3    = (const float*)d_in[16];
    float* out = (float*)d_out;

    static int smem_set = 0;
    if (!smem_set) {
        cudaFuncSetAttribute((const void*)gemm_in,
                             cudaFuncAttributeMaxDynamicSharedMemorySize, GEMM_SMEM);
        smem_set = 1;
    }

    gemm_in0<<<(BT * G4) / 256, 256>>>(x, W_ih0, b0);
    lstm_rec<<<256, 800>>>(W_hh0, 0, 1);

    dim3 ggrid(BT / GM, 4);
    for (int l = 0; l < NL - 1; l++) {
        int inSel  = (l % 2 == 0) ? 0 : 1;
        int outSel = 1 - inSel;
        gemm_in<<<ggrid, 256, GEMM_SMEM>>>(inSel, W_ih + (size_t)l * G4 * HH,
                                           bb + (size_t)l * G4);
        lstm_rec<<<256, 800>>>(W_hh + (size_t)l * G4 * HH, outSel,
                               (l == NL - 2) ? 0 : 1);
    }

    head_kernel<<<Bsz, 128>>>(0, gamma, beta, rmean, rvar,
                              W1, b1, W2, b2, W3, b3, out);
}

// round 12
// speedup vs baseline: 1.1909x; 1.1909x over previous
#include <cuda_runtime.h>
#include <cstdint>

#define Bsz 256
#define Tlen 512
#define Iin 5
#define HH 100
#define G4 400
#define NL 5
#define Oout 3
#define BT (Bsz*Tlen)

typedef unsigned long long ull;

#define FMA2(d, a, b, c) asm("fma.rn.f32x2 %0, %1, %2, %3;" : "=l"(d) : "l"(a), "l"(b), "l"(c))
#define ADDF2(d, a, b)   asm("add.rn.f32x2 %0, %1, %2;" : "=l"(d) : "l"(a), "l"(b))
#define PACK2(d, lo, hi) asm("mov.b64 %0, {%1, %2};" : "=l"(d) : "f"(lo), "f"(hi))
#define UNPACK2(lo, hi, v) asm("mov.b64 {%0, %1}, %2;" : "=f"(lo), "=f"(hi) : "l"(v))
#define TANHA(d, x) asm("tanh.approx.f32 %0, %1;" : "=f"(d) : "f"(x))

// ---------------------------------------------------------------------------
// Scratch
// ---------------------------------------------------------------------------
__device__ float g_gates[(size_t)BT * G4];
__device__ float g_hA[(size_t)BT * HH];
__device__ float g_hB[(size_t)BT * HH];

__device__ __forceinline__ float sigf(float x) {
    return __fdividef(1.0f, 1.0f + __expf(-x));
}

// ---------------------------------------------------------------------------
// Kernel 1a: layer-0 input projection (K=5) — round-6 exact
// ---------------------------------------------------------------------------
__global__ void gemm_in0(const float* __restrict__ x,
                         const float* __restrict__ Wih,
                         const float* __restrict__ bias)
{
    int idx = blockIdx.x * blockDim.x + threadIdx.x;
    int m = idx / G4;
    int n = idx - m * G4;
    const float* xr = x + (size_t)m * Iin;
    const float* wr = Wih + (size_t)n * Iin;
    float a = bias[n];
#pragma unroll
    for (int k = 0; k < Iin; k++) a += xr[k] * wr[k];
    g_gates[(size_t)idx] = a;
}

// ---------------------------------------------------------------------------
// Kernel 1b: layers 1..4 input projection — round-6 exact (verified 344us)
// ---------------------------------------------------------------------------
#define GM 64
#define GNJ 7
#define GN (16*GNJ)
#define KP 102
#define GEMM_SMEM ((GM + GN) * KP * 4)

__global__ __launch_bounds__(256)
void gemm_in(int inSel,
             const float* __restrict__ W,
             const float* __restrict__ bias)
{
    extern __shared__ float sm[];
    float* Xs = sm;
    float* Ws = sm + GM * KP;

    const float* X = inSel ? g_hB : g_hA;
    int tid = threadIdx.x;
    int tx = tid & 15;
    int ty = (tid >> 4) & 15;
    size_t m0 = (size_t)blockIdx.x * GM;
    int n0 = blockIdx.y * GN;

    {
        const float2* Xg = (const float2*)(X + m0 * 100);
        for (int idx = tid; idx < GM * 50; idx += 256) {
            int r = idx / 50, c = idx - r * 50;
            float2 v = Xg[(size_t)r * 50 + c];
            *(float2*)&Xs[r * KP + 2 * c] = v;
        }
        const float2* Wg = (const float2*)W;
        for (int idx = tid; idx < GN * 50; idx += 256) {
            int r = idx / 50, c = idx - r * 50;
            int gn = n0 + r;
            float2 v = (gn < G4) ? Wg[(size_t)gn * 50 + c] : make_float2(0.f, 0.f);
            *(float2*)&Ws[r * KP + 2 * c] = v;
        }
    }
    __syncthreads();

    ull acc[4][GNJ];
#pragma unroll
    for (int i = 0; i < 4; i++)
#pragma unroll
        for (int j = 0; j < GNJ; j++) PACK2(acc[i][j], 0.f, 0.f);

    const ull* xrow[4];
#pragma unroll
    for (int i = 0; i < 4; i++) xrow[i] = (const ull*)&Xs[(ty + 16 * i) * KP];
    const ull* wrow[GNJ];
#pragma unroll
    for (int j = 0; j < GNJ; j++) wrow[j] = (const ull*)&Ws[(tx + 16 * j) * KP];

#pragma unroll 5
    for (int k = 0; k < 50; k++) {
        ull dx[4], dw[GNJ];
#pragma unroll
        for (int i = 0; i < 4; i++) dx[i] = xrow[i][k];
#pragma unroll
        for (int j = 0; j < GNJ; j++) dw[j] = wrow[j][k];
#pragma unroll
        for (int i = 0; i < 4; i++)
#pragma unroll
            for (int j = 0; j < GNJ; j++)
                FMA2(acc[i][j], dx[i], dw[j], acc[i][j]);
    }

#pragma unroll
    for (int i = 0; i < 4; i++) {
        size_t m = m0 + ty + 16 * i;
#pragma unroll
        for (int j = 0; j < GNJ; j++) {
            int n = n0 + tx + 16 * j;
            if (n < G4) {
                float lo, hi;
                UNPACK2(lo, hi, acc[i][j]);
                g_gates[m * G4 + n] = lo + hi + bias[n];
            }
        }
    }
}

// ---------------------------------------------------------------------------
// Kernel 2: LSTM recurrence — round-10 structure (2 rows, 800 thr, 128 blk)
// with two tail changes:
//  * unified tanh.approx activation: sigma(x)=0.5+0.5*tanh(x/2) -> ONE
//    warp-uniform MUFU path for all gates (6 warp-MUFU -> 2 per step)
//  * single xor-shuffle K-half exchange (each lane sends the partial its
//    partner needs) instead of two
// ---------------------------------------------------------------------------
__global__ __launch_bounds__(800, 1)
void lstm_rec(const float* __restrict__ W_hh,   // [400,100]
              int outSel, int storeAll)
{
    __shared__ __align__(16) float hbuf[2][2][104];  // [parity][row][unit(+pad)]

    const int tid  = threadIdx.x;
    const int u    = tid >> 3;
    const int s    = (tid >> 1) & 3;    // 0=i 1=f 2=g 3=o
    const int half = tid & 1;
    const int grow = s * 100 + u;
    const int b0   = blockIdx.x * 2;
    const int lane = tid & 31;
    const int lb   = lane & ~7;
    const int cbase = 13 * half;

    // activation constants: gate s==2 is tanh, others sigmoid via tanh(x/2)
    const float k1 = (s == 2) ? 1.0f : 0.5f;   // input scale
    const float k2 = (s == 2) ? 1.0f : 0.5f;   // output scale
    const float k3 = (s == 2) ? 0.0f : 0.5f;   // output offset

    // half of the weight row -> 26 packed regs (chunk 25 = zeros)
    ull w2[26];
    {
        const float4* wr = (const float4*)(W_hh + (size_t)grow * HH);
#pragma unroll
        for (int i = 0; i < 13; i++) {
            int cc = cbase + i;
            float4 v = (cc < 25) ? wr[cc] : make_float4(0.f, 0.f, 0.f, 0.f);
            PACK2(w2[2 * i],     v.x, v.y);
            PACK2(w2[2 * i + 1], v.z, v.w);
        }
    }

    if (tid < 416) ((float*)hbuf)[tid] = 0.f;
    float c = 0.f;                       // live in lanes (tid&7)<2; row = half

    const float* gp0 = g_gates + (size_t)b0 * Tlen * G4;
    const float* gp1 = gp0 + (size_t)Tlen * G4;
    float* hout = outSel ? g_hB : g_hA;
    float* hsrow = hout + (size_t)(b0 + half) * Tlen * HH;   // this lane's row

    float pg0 = gp0[grow];
    float pg1 = gp1[grow];
    __syncthreads();

    for (int t = 0; t < Tlen; t++) {
        const int p = t & 1;
        const float cur0 = (half == 0) ? pg0 : 0.f;   // preact added once/pair
        const float cur1 = (half == 0) ? pg1 : 0.f;

        // dual-row half-dot
        ull a0, a1, e0, e1;
        PACK2(a0, cur0, 0.f); PACK2(a1, 0.f, 0.f);
        PACK2(e0, cur1, 0.f); PACK2(e1, 0.f, 0.f);
        {
            const ulonglong2* hA = (const ulonglong2*)hbuf[p][0];
            const ulonglong2* hB = (const ulonglong2*)hbuf[p][1];
#pragma unroll
            for (int i = 0; i < 13; i++) {
                ulonglong2 vA = hA[cbase + i];
                ulonglong2 vB = hB[cbase + i];
                FMA2(a0, w2[2 * i],     vA.x, a0);
                FMA2(a1, w2[2 * i + 1], vA.y, a1);
                FMA2(e0, w2[2 * i],     vB.x, e0);
                FMA2(e1, w2[2 * i + 1], vB.y, e1);
            }
        }
        // prefetch next step's pre-activations (verified position: after dot,
        // all lanes, unpredicated)
        {
            int tn = (t + 1 < Tlen) ? (t + 1) : t;
            pg0 = gp0[(size_t)tn * G4 + grow];
            pg1 = gp1[(size_t)tn * G4 + grow];
        }
        ADDF2(a0, a0, a1);
        ADDF2(e0, e0, e1);
        float q0, q1;
        UNPACK2(q0, q1, a0); float part0 = q0 + q1;   // row0 partial (my K-half)
        UNPACK2(q0, q1, e0); float part1 = q0 + q1;   // row1 partial (my K-half)

        // single-shuffle K-half exchange: send the partial the PARTNER needs
        // (partner activates the other row); receive the one I need.
        float mypart = half ? part1 : part0;
        float send   = half ? part0 : part1;
        float recv   = __shfl_xor_sync(0xFFFFFFFFu, send, 1);
        float myfull = mypart + recv;

        // unified tanh.approx activation (warp-uniform single MUFU path)
        float th;
        TANHA(th, k1 * myfull);
        float v = fmaf(k2, th, k3);

        // gather f,g,o for my row (source lanes lb+2/4/6, +half selects row)
        float fv = __shfl_sync(0xFFFFFFFFu, v, lb + 2 + half);
        float gv = __shfl_sync(0xFFFFFFFFu, v, lb + 4 + half);
        float ov = __shfl_sync(0xFFFFFFFFu, v, lb + 6 + half);

        // state update: lane lb -> row0, lane lb+1 -> row1
        const int pn = p ^ 1;
        if ((tid & 7) < 2) {             // s==0; v = my row's input gate
            c = fv * c + v * gv;
            float tc;
            TANHA(tc, c);
            float h = ov * tc;
            hbuf[pn][half][u] = h;
            if (storeAll || t == Tlen - 1) hsrow[(size_t)t * HH + u] = h;
        }
        __syncthreads();
    }
}

// ---------------------------------------------------------------------------
// Kernel 3: BN + MLP head (accurate activations; negligible cost)
// ---------------------------------------------------------------------------
__global__ void head_kernel(int inSel,
                            const float* __restrict__ gamma,
                            const float* __restrict__ beta,
                            const float* __restrict__ rmean,
                            const float* __restrict__ rvar,
                            const float* __restrict__ W1, const float* __restrict__ b1,
                            const float* __restrict__ W2, const float* __restrict__ b2,
                            const float* __restrict__ W3, const float* __restrict__ b3,
                            float* __restrict__ out)
{
    __shared__ float xa[HH], ya[HH];
    const float* hseq = inSel ? g_hB : g_hA;
    int b = blockIdx.x, tid = threadIdx.x;

    if (tid < HH) {
        float v = hseq[((size_t)b * Tlen + (Tlen - 1)) * HH + tid];
        xa[tid] = (v - rmean[tid]) * rsqrtf(rvar[tid] + 1e-5f) * gamma[tid] + beta[tid];
    }
    __syncthreads();
    if (tid < HH) {
        float a = b1[tid];
#pragma unroll 4
        for (int k = 0; k < HH; k++) a += xa[k] * W1[(size_t)tid * HH + k];
        ya[tid] = fmaxf(a, 0.0f);
    }
    __syncthreads();
    if (tid < HH) {
        float a = b2[tid];
#pragma unroll 4
        for (int k = 0; k < HH; k++) a += ya[k] * W2[(size_t)tid * HH + k];
        xa[tid] = fmaxf(a, 0.0f);
    }
    __syncthreads();
    if (tid < Oout) {
        float a = b3[tid];
#pragma unroll 4
        for (int k = 0; k < HH; k++) a += xa[k] * W3[(size_t)tid * HH + k];
        out[(size_t)b * Oout + tid] = a;
    }
}

// ---------------------------------------------------------------------------
// kernel_launch
// ---------------------------------------------------------------------------
extern "C" void kernel_launch(void* const* d_in, const int* in_sizes, int n_in,
                              void* d_out, int out_size)
{
    const float* x     = (const float*)d_in[0];
    const float* W_ih0 = (const float*)d_in[1];
    const float* W_hh0 = (const float*)d_in[2];
    const float* b0    = (const float*)d_in[3];
    const float* W_ih  = (const float*)d_in[4];
    const float* W_hh  = (const float*)d_in[5];
    const float* bb    = (const float*)d_in[6];
    const float* gamma = (const float*)d_in[7];
    const float* beta  = (const float*)d_in[8];
    const float* rmean = (const float*)d_in[9];
    const float* rvar  = (const float*)d_in[10];
    const float* W1    = (const float*)d_in[11];
    const float* b1    = (const float*)d_in[12];
    const float* W2    = (const float*)d_in[13];
    const float* b2    = (const float*)d_in[14];
    const float* W3    = (const float*)d_in[15];
    const float* b3    = (const float*)d_in[16];
    float* out = (float*)d_out;

    static int smem_set = 0;
    if (!smem_set) {
        cudaFuncSetAttribute((const void*)gemm_in,
                             cudaFuncAttributeMaxDynamicSharedMemorySize, GEMM_SMEM);
        smem_set = 1;
    }

    gemm_in0<<<(BT * G4) / 256, 256>>>(x, W_ih0, b0);
    lstm_rec<<<128, 800>>>(W_hh0, 0, 1);

    dim3 ggrid(BT / GM, 4);
    for (int l = 0; l < NL - 1; l++) {
        int inSel  = (l % 2 == 0) ? 0 : 1;
        int outSel = 1 - inSel;
        gemm_in<<<ggrid, 256, GEMM_SMEM>>>(inSel, W_ih + (size_t)l * G4 * HH,
                                           bb + (size_t)l * G4);
        lstm_rec<<<128, 800>>>(W_hh + (size_t)l * G4 * HH, outSel,
                               (l == NL - 2) ? 0 : 1);
    }

    head_kernel<<<Bsz, 128>>>(0, gamma, beta, rmean, rvar,
                              W1, b1, W2, b2, W3, b3, out);
}